// round 5
// baseline (speedup 1.0000x reference)
#include <cuda_runtime.h>

// inputs: float32 [16, 64, 256, 256] NCHW
#define NB        16
#define NC        64
#define HW4       16384              // float4 per (n,c) slice
#define SLICE4    (NC * HW4)         // 1,048,576 float4 per n
#define CHUNKS    64                 // hw4 chunks of 256 float4
#define TPB       256
#define EPS       1e-5f

#define NG        8                  // channel groups
#define CPG       8                  // channels per group
#define GSIZE4    (CPG * NB * HW4)   // 2,097,152 float4 per group
#define GTILES    (CPG * CHUNKS)     // 512 tiles per group
#define PBLK      296                // producer blocks (even bids)
#define CBLK      296                // consumer blocks (odd bids)
#define NBLK      (PBLK + CBLK)      // 592 = 148 SMs * 4

__device__ float g_psum[NC * CHUNKS];
__device__ float g_psq [NC * CHUNKS];
__device__ float g_scale[NC];        // rstd
__device__ float g_bias [NC];        // -mean * rstd
__device__ int   g_done [NG];        // producer tiles completed per group
__device__ int   g_ready[NG];        // scales published
__device__ int   c_done [NG];        // consumer blocks finished per group

__global__ void zero_flags_kernel() {
    int t = threadIdx.x;
    if (t < NG) { g_done[t] = 0; g_ready[t] = 0; c_done[t] = 0; }
}

__global__ void __launch_bounds__(TPB, 4)
fused_kernel(const float4* __restrict__ in, float4* __restrict__ out) {
    const int tid  = threadIdx.x;
    const int lane = tid & 31;
    const int wid  = tid >> 5;

    __shared__ float sh_s[8], sh_q[8];
    __shared__ float sh_scale[CPG], sh_bias[CPG];

    if ((blockIdx.x & 1) == 0) {
        // ─── PRODUCER: reduce, group by group ───
        const int p = blockIdx.x >> 1;            // [0, PBLK)

        for (int g = 0; g < NG; g++) {
            // throttle: stay <= 2 groups ahead of consumers (bound L2 footprint)
            if (g >= 2) {
                if (tid == 0) {
                    while (*((volatile int*)&c_done[g - 2]) < CBLK) __nanosleep(64);
                }
                __syncthreads();
            }
            const int c0 = g * CPG;

            for (int t = p; t < GTILES; t += PBLK) {
                const int c     = c0 + (t >> 6);
                const int chunk = t & 63;
                const float4* ptr = in + (size_t)c * HW4 + chunk * TPB + tid;

                float s = 0.0f, q = 0.0f;
                float4 v[8];
                #pragma unroll
                for (int n = 0; n < 8; n++)
                    v[n] = __ldcg(&ptr[(size_t)n * SLICE4]);
                #pragma unroll
                for (int n = 0; n < 8; n++) {
                    s += (v[n].x + v[n].y) + (v[n].z + v[n].w);
                    q += (v[n].x * v[n].x + v[n].y * v[n].y)
                       + (v[n].z * v[n].z + v[n].w * v[n].w);
                }
                #pragma unroll
                for (int n = 0; n < 8; n++)
                    v[n] = __ldcg(&ptr[(size_t)(n + 8) * SLICE4]);
                #pragma unroll
                for (int n = 0; n < 8; n++) {
                    s += (v[n].x + v[n].y) + (v[n].z + v[n].w);
                    q += (v[n].x * v[n].x + v[n].y * v[n].y)
                       + (v[n].z * v[n].z + v[n].w * v[n].w);
                }

                #pragma unroll
                for (int off = 16; off > 0; off >>= 1) {
                    s += __shfl_down_sync(0xffffffffu, s, off);
                    q += __shfl_down_sync(0xffffffffu, q, off);
                }
                if (lane == 0) { sh_s[wid] = s; sh_q[wid] = q; }
                __syncthreads();

                if (wid == 0) {
                    s = (lane < 8) ? sh_s[lane] : 0.0f;
                    q = (lane < 8) ? sh_q[lane] : 0.0f;
                    #pragma unroll
                    for (int off = 4; off > 0; off >>= 1) {
                        s += __shfl_down_sync(0xffffffffu, s, off);
                        q += __shfl_down_sync(0xffffffffu, q, off);
                    }
                    bool last = false;
                    if (lane == 0) {
                        g_psum[c * CHUNKS + chunk] = s;
                        g_psq [c * CHUNKS + chunk] = q;
                        __threadfence();
                        int old = atomicAdd(&g_done[g], 1);
                        last = (old == GTILES - 1);
                    }
                    last = __shfl_sync(0xffffffffu, (int)last, 0);
                    if (last) {
                        __threadfence();   // acquire partials from other blocks
                        if (lane < CPG) {
                            const int cc = c0 + lane;
                            float ss = 0.0f, qq = 0.0f;
                            #pragma unroll 8
                            for (int k = 0; k < CHUNKS; k++) {
                                ss += g_psum[cc * CHUNKS + k];
                                qq += g_psq [cc * CHUNKS + k];
                            }
                            const float invN = 1.0f / (float)(NB * HW4 * 4);
                            const float mean = ss * invN;
                            const float rstd = rsqrtf(qq * invN - mean * mean + EPS);
                            g_scale[cc] = rstd;
                            g_bias [cc] = -mean * rstd;
                        }
                        __syncwarp();
                        __threadfence();
                        if (lane == 0) atomicExch(&g_ready[g], 1);
                    }
                }
                __syncthreads();
            }
        }
    } else {
        // ─── CONSUMER: normalize, group by group ───
        const int q = blockIdx.x >> 1;            // [0, CBLK)
        const int CT = CBLK * TPB;                // 75776 threads

        for (int g = 0; g < NG; g++) {
            if (tid == 0) {
                while (*((volatile int*)&g_ready[g]) == 0) __nanosleep(64);
            }
            __syncthreads();
            __threadfence();
            const int c0 = g * CPG;
            if (tid < CPG) {
                sh_scale[tid] = g_scale[c0 + tid];
                sh_bias [tid] = g_bias [c0 + tid];
            }
            __syncthreads();

            const int base4 = c0 * HW4;
            int j = q * TPB + tid;
            #pragma unroll 4
            for (int k = 0; k < 28; k++, j += CT) {
                if (j < GSIZE4) {
                    const int n   = j >> 17;             // j / (CPG*HW4)
                    const int rem = j & (CPG * HW4 - 1);
                    const int cl  = rem >> 14;           // local channel
                    const int idx = n * SLICE4 + base4 + rem;
                    const float scale = sh_scale[cl];
                    const float bias  = sh_bias[cl];
                    float4 v = in[idx];
                    float4 o;
                    o.x = fmaf(v.x, scale, bias);
                    o.y = fmaf(v.y, scale, bias);
                    o.z = fmaf(v.z, scale, bias);
                    o.w = fmaf(v.w, scale, bias);
                    __stcs(&out[idx], o);
                }
            }
            __syncthreads();
            if (tid == 0) atomicAdd(&c_done[g], 1);
        }
    }
}

extern "C" void kernel_launch(void* const* d_in, const int* in_sizes, int n_in,
                              void* d_out, int out_size) {
    const float4* in  = (const float4*)d_in[0];
    float4*       out = (float4*)d_out;

    zero_flags_kernel<<<1, 32>>>();
    fused_kernel<<<NBLK, TPB>>>(in, out);
}

// round 6
// speedup vs baseline: 1.2566x; 1.2566x over previous
#include <cuda_runtime.h>

// inputs: float32 [16, 64, 256, 256] NCHW
#define NB      16
#define NC      64
#define HW4     16384                 // float4 per (n,c) slice
#define SLICE4  (NC * HW4)            // float4 per batch image
#define TPB     256
#define EPS     1e-5f

#define NG      8                     // channel groups
#define CPG     8                     // channels per group (33.5 MB/group)
#define NBLK    512                   // 64 blocks per channel, all co-resident
#define ITERS   16                    // float4 per thread per group

__device__ float g_sum[NC];
__device__ float g_sq [NC];
__device__ float g_scale[NC];         // rstd
__device__ float g_bias [NC];         // -mean*rstd
__device__ int   g_done [NG];
__device__ int   g_ready[NG];

__global__ void init_kernel() {
    const int t = threadIdx.x;
    if (t < NC) { g_sum[t] = 0.0f; g_sq[t] = 0.0f; }
    if (t < NG) { g_done[t] = 0; g_ready[t] = 0; }
}

__global__ void __launch_bounds__(TPB, 4)
fused_kernel(const float4* __restrict__ in, float4* __restrict__ out) {
    const int tid  = threadIdx.x;
    const int lane = tid & 31;
    const int wid  = tid >> 5;

    // Block -> tile map: 64 blocks per channel; block covers one quarter of
    // one (n, c) slice: contiguous 4096 float4 (64 KB).
    const int cidx = blockIdx.x >> 6;          // channel within group [0,8)
    const int b    = blockIdx.x & 63;          // block within channel
    const int n    = b >> 2;                   // batch index
    const int hw0  = (b & 3) * 4096;           // hw4 offset

    __shared__ float sh_s[8], sh_q[8];
    __shared__ float sh_sb[2];

    for (int g = 0; g < NG; g++) {
        const int c = g * CPG + cidx;
        const size_t base = (size_t)n * SLICE4 + (size_t)c * HW4 + hw0 + tid;

        // ── reduce my tile (default caching: lines land in L1/L2) ──
        float s = 0.0f, q = 0.0f;
        {
            float4 v[8];
            #pragma unroll
            for (int k = 0; k < 8; k++) v[k] = in[base + k * TPB];
            #pragma unroll
            for (int k = 0; k < 8; k++) {
                s += (v[k].x + v[k].y) + (v[k].z + v[k].w);
                q += (v[k].x * v[k].x + v[k].y * v[k].y)
                   + (v[k].z * v[k].z + v[k].w * v[k].w);
            }
            #pragma unroll
            for (int k = 0; k < 8; k++) v[k] = in[base + (k + 8) * TPB];
            #pragma unroll
            for (int k = 0; k < 8; k++) {
                s += (v[k].x + v[k].y) + (v[k].z + v[k].w);
                q += (v[k].x * v[k].x + v[k].y * v[k].y)
                   + (v[k].z * v[k].z + v[k].w * v[k].w);
            }
        }

        #pragma unroll
        for (int off = 16; off > 0; off >>= 1) {
            s += __shfl_down_sync(0xffffffffu, s, off);
            q += __shfl_down_sync(0xffffffffu, q, off);
        }
        if (lane == 0) { sh_s[wid] = s; sh_q[wid] = q; }
        __syncthreads();

        if (tid == 0) {
            float ss = sh_s[0], qq = sh_q[0];
            #pragma unroll
            for (int w = 1; w < 8; w++) { ss += sh_s[w]; qq += sh_q[w]; }
            atomicAdd(&g_sum[c], ss);
            atomicAdd(&g_sq [c], qq);
            __threadfence();
            const int old = atomicAdd(&g_done[g], 1);
            if (old == NBLK - 1) {
                // last arriver: finalize this group's 8 channels
                __threadfence();
                const float invN = 1.0f / (float)(NB * HW4 * 4);
                #pragma unroll
                for (int cc = g * CPG; cc < g * CPG + CPG; cc++) {
                    const float mean = g_sum[cc] * invN;
                    const float rstd = rsqrtf(g_sq[cc] * invN - mean * mean + EPS);
                    g_scale[cc] = rstd;
                    g_bias [cc] = -mean * rstd;
                }
                __threadfence();
                atomicExch(&g_ready[g], 1);
            }
            // wait for stats (cheap: usually already set by the time we spin)
            while (*((volatile int*)&g_ready[g]) == 0) __nanosleep(64);
            __threadfence();
            sh_sb[0] = g_scale[c];
            sh_sb[1] = g_bias [c];
        }
        __syncthreads();

        const float scale = sh_sb[0];
        const float bias  = sh_sb[1];

        // ── normalize the SAME tile (reads served by L1/L2) ──
        #pragma unroll
        for (int k = 0; k < ITERS; k++) {
            const size_t idx = base + k * TPB;
            float4 v = in[idx];
            float4 o;
            o.x = fmaf(v.x, scale, bias);
            o.y = fmaf(v.y, scale, bias);
            o.z = fmaf(v.z, scale, bias);
            o.w = fmaf(v.w, scale, bias);
            out[idx] = o;
        }
        __syncthreads();   // protect sh_* reuse next group
    }
}

extern "C" void kernel_launch(void* const* d_in, const int* in_sizes, int n_in,
                              void* d_out, int out_size) {
    const float4* in  = (const float4*)d_in[0];
    float4*       out = (float4*)d_out;

    init_kernel<<<1, 64>>>();
    fused_kernel<<<NBLK, TPB>>>(in, out);
}

// round 7
// speedup vs baseline: 1.4065x; 1.1193x over previous
#include <cuda_runtime.h>

// inputs: float32 [16, 64, 256, 256] NCHW
#define NB      16
#define NC      64
#define HW4     16384                 // float4 per (n,c) slice
#define SLICE4  (NC * HW4)
#define TPB     256
#define EPS     1e-5f

#define NR      8                     // rounds (channel groups of 8)
#define CPR     8                     // channels per round
#define BPC     64                    // blocks per channel
#define NBLK    512                   // all co-resident (<= 148*4 slots)
#define ITERS   16                    // float4 per thread per tile (64 KB tile)

__device__ float g_sum[NC];
__device__ float g_sq [NC];
__device__ float g_scale[NC];         // rstd
__device__ float g_bias [NC];         // -mean*rstd
__device__ int   g_done [NC];         // per-channel reduce arrivals
__device__ int   g_ready[NC];         // per-channel stats published

__global__ void init_kernel() {
    const int t = threadIdx.x;
    if (t < NC) {
        g_sum[t] = 0.0f; g_sq[t] = 0.0f;
        g_done[t] = 0;   g_ready[t] = 0;
    }
}

// Reduce one 64 KB tile of channel c; fold into per-channel sums; the last
// arriving block of the channel finalizes scale/bias and raises ready[c].
__device__ __forceinline__ void reduce_tile(
    const float4* __restrict__ in, size_t base, int c,
    float* sh_s, float* sh_q, int tid, int lane, int wid)
{
    float s = 0.0f, q = 0.0f;
    {
        float4 v[8];
        #pragma unroll
        for (int k = 0; k < 8; k++) v[k] = in[base + k * TPB];
        #pragma unroll
        for (int k = 0; k < 8; k++) {
            s += (v[k].x + v[k].y) + (v[k].z + v[k].w);
            q += (v[k].x * v[k].x + v[k].y * v[k].y)
               + (v[k].z * v[k].z + v[k].w * v[k].w);
        }
        #pragma unroll
        for (int k = 0; k < 8; k++) v[k] = in[base + (k + 8) * TPB];
        #pragma unroll
        for (int k = 0; k < 8; k++) {
            s += (v[k].x + v[k].y) + (v[k].z + v[k].w);
            q += (v[k].x * v[k].x + v[k].y * v[k].y)
               + (v[k].z * v[k].z + v[k].w * v[k].w);
        }
    }

    #pragma unroll
    for (int off = 16; off > 0; off >>= 1) {
        s += __shfl_down_sync(0xffffffffu, s, off);
        q += __shfl_down_sync(0xffffffffu, q, off);
    }
    if (lane == 0) { sh_s[wid] = s; sh_q[wid] = q; }
    __syncthreads();

    if (tid == 0) {
        float ss = sh_s[0], qq = sh_q[0];
        #pragma unroll
        for (int w = 1; w < 8; w++) { ss += sh_s[w]; qq += sh_q[w]; }
        atomicAdd(&g_sum[c], ss);
        atomicAdd(&g_sq [c], qq);
        __threadfence();
        const int old = atomicAdd(&g_done[c], 1);
        if (old == BPC - 1) {
            __threadfence();
            const float invN = 1.0f / (float)(NB * HW4 * 4);
            const float mean = g_sum[c] * invN;
            const float rstd = rsqrtf(g_sq[c] * invN - mean * mean + EPS);
            g_scale[c] = rstd;
            g_bias [c] = -mean * rstd;
            __threadfence();
            atomicExch(&g_ready[c], 1);
        }
    }
    __syncthreads();   // sh_s/sh_q safe for reuse
}

__global__ void __launch_bounds__(TPB, 4)
fused_kernel(const float4* __restrict__ in, float4* __restrict__ out) {
    const int tid  = threadIdx.x;
    const int lane = tid & 31;
    const int wid  = tid >> 5;

    // Block -> tile: 64 blocks per channel; tile = quarter of one (n,c) slice.
    const int cidx = blockIdx.x >> 6;          // channel within round [0,8)
    const int b    = blockIdx.x & 63;
    const int n    = b >> 2;
    const int hw0  = (b & 3) * 4096;

    __shared__ float sh_s[8], sh_q[8];
    __shared__ float sh_sb[2];

    const size_t tbase = (size_t)n * SLICE4 + hw0 + tid;

    // ── pipeline fill: reduce round 0 ──
    {
        const int c0 = cidx;                   // round 0 channel
        reduce_tile(in, tbase + (size_t)c0 * HW4, c0, sh_s, sh_q, tid, lane, wid);
    }

    for (int g = 0; g < NR; g++) {
        const int c = g * CPR + cidx;

        // ── reduce next round first (hides the ready-wait below) ──
        if (g + 1 < NR) {
            const int cn = (g + 1) * CPR + cidx;
            reduce_tile(in, tbase + (size_t)cn * HW4, cn, sh_s, sh_q, tid, lane, wid);
        }

        // ── wait for my channel's stats (usually already set) ──
        if (tid == 0) {
            while (*((volatile int*)&g_ready[c]) == 0) __nanosleep(32);
            __threadfence();
            sh_sb[0] = g_scale[c];
            sh_sb[1] = g_bias [c];
        }
        __syncthreads();
        const float scale = sh_sb[0];
        const float bias  = sh_sb[1];

        // ── normalize my round-g tile (reads L2/L1-resident) ──
        const size_t base = tbase + (size_t)c * HW4;
        #pragma unroll
        for (int k = 0; k < ITERS; k++) {
            const size_t idx = base + k * TPB;
            float4 v = in[idx];
            float4 o;
            o.x = fmaf(v.x, scale, bias);
            o.y = fmaf(v.y, scale, bias);
            o.z = fmaf(v.z, scale, bias);
            o.w = fmaf(v.w, scale, bias);
            out[idx] = o;
        }
        __syncthreads();   // sh_sb safe for next round
    }
}

extern "C" void kernel_launch(void* const* d_in, const int* in_sizes, int n_in,
                              void* d_out, int out_size) {
    const float4* in  = (const float4*)d_in[0];
    float4*       out = (float4*)d_out;

    init_kernel<<<1, 64>>>();
    fused_kernel<<<NBLK, TPB>>>(in, out);
}